// round 8
// baseline (speedup 1.0000x reference)
#include <cuda_runtime.h>
#include <cuda_bf16.h>
#include <math.h>

#define N_Q   4098
#define N_KV  4099
#define CDIM  384
#define HEADS 6
#define HDIM  64

// fragment-major global layouts (per head)
#define HSTR_Q 270336           // 264 q16-groups * 1024 words
#define HSTR_K 266240           // 65 key-tiles  * 4096 words

// ---------------- scratch (device globals; allocation-free) ----------------
__device__ __align__(16) float g_pp[64 * CDIM];     // pooling partials
__device__ float  g_cntp[64];                       // count partials
__device__ __align__(16) float g_back[CDIM];        // back token
__device__ int    g_idx[N_KV];                      // kept key -> source row
__device__ int    g_M;                              // number of kept keys
__device__ __align__(16) unsigned g_qf[HEADS * HSTR_Q];  // Q A-frags (tf32, prescaled 1/8)
__device__ __align__(16) unsigned g_kf[HEADS * HSTR_K];  // K B-frags (tf32)
__device__ __align__(16) unsigned g_vf[HEADS * HSTR_K];  // V B-frags (tf32)
__device__ __align__(16) float g_o[N_Q * CDIM];

// ---------------- helpers ---------------------------------------------------
__device__ __forceinline__ unsigned f2tf(float x)
{
    unsigned r;
    asm("cvt.rna.tf32.f32 %0, %1;" : "=r"(r) : "f"(x));
    return r;
}

__device__ __forceinline__ void mma8(float* c, const unsigned* a, const unsigned* b)
{
    asm volatile(
        "mma.sync.aligned.m16n8k8.row.col.f32.tf32.tf32.f32 "
        "{%0,%1,%2,%3}, {%4,%5,%6,%7}, {%8,%9}, {%0,%1,%2,%3};\n"
        : "+f"(c[0]), "+f"(c[1]), "+f"(c[2]), "+f"(c[3])
        : "r"(a[0]), "r"(a[1]), "r"(a[2]), "r"(a[3]), "r"(b[0]), "r"(b[1]));
}

__device__ __forceinline__ void cp16(unsigned dst, const void* src)
{
    asm volatile("cp.async.ca.shared.global [%0], [%1], 16;"
                 :: "r"(dst), "l"(src));
}
#define CP_COMMIT() asm volatile("cp.async.commit_group;")
#define CP_WAIT(n)  asm volatile("cp.async.wait_group %0;" :: "n"(n))

// Q A-fragment word index (row r, global col)
__device__ __forceinline__ int qf_idx(int r, int col)
{
    const int h = col >> 6, d = col & 63;
    return h * HSTR_Q
         + ((((r >> 4) * 8 + (d >> 3)) * 32 + (r & 7) * 4 + (d & 3)) << 2)
         + ((r >> 3) & 1) + 2 * ((d >> 2) & 1);
}
// K B-fragment word index (key row kr, global col)
__device__ __forceinline__ int kf_idx(int kr, int col)
{
    const int h = col >> 6, d = col & 63;
    return h * HSTR_K + ((kr >> 6) << 12)
         + (((((kr >> 3) & 7) * 8 + (d >> 3)) * 32 + (kr & 7) * 4 + (d & 3)) << 1)
         + ((d >> 2) & 1);
}
// V B-fragment word index (key row kr, global col)
__device__ __forceinline__ int vf_idx(int kr, int col)
{
    const int h = col >> 6, d = col & 63;
    return h * HSTR_K + ((kr >> 6) << 12)
         + ((((d >> 3) * 8 + ((kr >> 3) & 7)) * 32 + (d & 7) * 4 + (kr & 3)) << 1)
         + ((kr >> 2) & 1);
}

// ---------------- 1) background pooling (deterministic, 2-stage) -----------
__global__ void pool_kernel(const float* __restrict__ x, const float* __restrict__ mask)
{
    const int c  = threadIdx.x;            // 384 threads
    const int n0 = blockIdx.x * 64;
    float s = 0.f;
#pragma unroll 8
    for (int i = 0; i < 64; i++) {
        const int n = n0 + i;
        const float rev = (mask[n] < 0.5f) ? 1.f : 0.f;
        s += rev * x[(1 + n) * CDIM + c];
    }
    g_pp[blockIdx.x * CDIM + c] = s;
    if (c == 0) {
        float cc = 0.f;
        for (int i = 0; i < 64; i++) cc += (mask[n0 + i] < 0.5f) ? 1.f : 0.f;
        g_cntp[blockIdx.x] = cc;
    }
}

__global__ void back_finalize_kernel()
{
    const int c = threadIdx.x;             // 384 threads
    float cnt = 0.f;
    for (int b = 0; b < 64; b++) cnt += g_cntp[b];
    float s = 0.f;
    for (int b = 0; b < 64; b++) s += g_pp[b * CDIM + c];
    g_back[c] = s / (cnt + 1e-10f);
}

// ---------------- 2) kept-key compaction (1-block prefix scan) -------------
__global__ void scan_kernel(const float* __restrict__ mask,
                            const float* __restrict__ mask_block)
{
    __shared__ int sc[1024];
    const int t = threadIdx.x;
    const int base = t * 5;
    int flags[5];
    int cnt = 0;
#pragma unroll
    for (int e = 0; e < 5; e++) {
        int r = base + e;
        int f = 0;
        if (r < N_KV) {
            float mv = (r >= 1 && r <= N_Q - 2) ? mask[r - 1] : mask_block[r];
            f = (mv >= 0.5f) ? 1 : 0;
        }
        flags[e] = f;
        cnt += f;
    }
    sc[t] = cnt;
    __syncthreads();
    for (int off = 1; off < 1024; off <<= 1) {
        int v = (t >= off) ? sc[t - off] : 0;
        __syncthreads();
        sc[t] += v;
        __syncthreads();
    }
    int o = sc[t] - cnt;
#pragma unroll
    for (int e = 0; e < 5; e++)
        if (flags[e]) g_idx[o++] = base + e;
    if (t == 1023) g_M = sc[1023];
}

// ---------------- 3) tf32 projection GEMM (fragment-major smem) ------------
// mode 0: q = (x + pos[:N]) @ Wq^T * 1/8    -> g_qf (A-frag layout)
// mode 1: k = (kv_x[idx] + pos[idx]) @ Wk^T -> g_kf (B-frag layout, gathered)
// mode 2: v = kv_x[idx] @ Wv^T              -> g_vf (B-frag layout, gathered)
// mode 3: o = g_o @ Wp^T + bp               -> d_out (fp32, row-major)
// block tile 128(M) x 64(N), k-tile 32, 8 warps in 4(M) x 2(N)
// smem: A-frags [2][8sub][4ks][32lane][4slot] + W-frags [2][8nsub][4ks][32lane][2]
#define PROJ_SMEM ((2 * 4096 + 2 * 2048) * (int)sizeof(unsigned))

__global__ __launch_bounds__(256)
void proj_tc(int base_mode,
             const float* __restrict__ x, const float* __restrict__ pos,
             const float* __restrict__ Wq_, const float* __restrict__ Wk_,
             const float* __restrict__ Wv_, const float* __restrict__ Wp_,
             const float* __restrict__ bias,
             float* __restrict__ out_param)
{
    extern __shared__ unsigned smP[];
    unsigned* smA = smP;                    // 2 x 4096 words
    unsigned* smW = smP + 2 * 4096;         // 2 x 2048 words

    const int mode = base_mode + blockIdx.z;
    const int rows = (mode == 1 || mode == 2) ? g_M : N_Q;
    const int m0 = blockIdx.x * 128;
    if (m0 >= rows) return;
    const int j0 = blockIdx.y * 64;

    const float* W =
        (mode == 0) ? Wq_ : (mode == 1) ? Wk_ : (mode == 2) ? Wv_ : Wp_;

    const int tid  = threadIdx.x;
    const int warp = tid >> 5, lane = tid & 31;
    const int wm = warp >> 1, wn = warp & 1;
    const int g = lane >> 2, tl = lane & 3;

    // ---- per-thread source pointers ----
    const float* pA[4];
    const float* pP[4];
    int rA[4];
#pragma unroll
    for (int i = 0; i < 4; i++) {
        const int lin = tid + i * 256;
        rA[i] = lin >> 3;                  // 0..127
        const int mg = m0 + rA[i];
        pA[i] = nullptr; pP[i] = nullptr;
        if (mg < rows) {
            if (mode == 0) {
                pA[i] = x + mg * CDIM;
                pP[i] = pos + mg * CDIM;
            } else if (mode == 3) {
                pA[i] = g_o + mg * CDIM;
            } else {
                const int src = g_idx[mg];
                pA[i] = (src < N_Q) ? (x + src * CDIM) : g_back;
                if (mode == 1) pP[i] = pos + src * CDIM;
            }
        }
    }
    const float* pW[2];
    int rW[2];
#pragma unroll
    for (int i = 0; i < 2; i++) {
        const int lin = tid + i * 256;
        rW[i] = lin >> 3;                  // 0..63
        pW[i] = W + (j0 + rW[i]) * CDIM;
    }
    const int cA   = (tid & 7) * 4;        // k-offset within 32-tile
    const int ksA  = cA >> 3;              // fragment k-slice
    const int dhiA = (cA >> 2) & 1;        // slot/word-half selector

    // precomputed fragment-store bases (word indices, t'-stride known)
    int baseA[4];
#pragma unroll
    for (int i = 0; i < 4; i++)
        baseA[i] = (((rA[i] >> 4) * 4 + ksA) * 32 + (rA[i] & 7) * 4) * 4
                 + ((rA[i] >> 3) & 1) + 2 * dhiA;
    int baseW[2];
#pragma unroll
    for (int i = 0; i < 2; i++)
        baseW[i] = (((rW[i] >> 3) * 4 + ksA) * 32 + (rW[i] & 7) * 4) * 2 + dhiA;

    float4 aReg[4], pReg[4], wReg[2];

#define PREFETCH(kt)                                                          \
    do {                                                                      \
        _Pragma("unroll")                                                     \
        for (int i = 0; i < 4; i++) {                                         \
            aReg[i] = pA[i] ? *(const float4*)(pA[i] + (kt) + cA)             \
                            : make_float4(0.f, 0.f, 0.f, 0.f);                \
            pReg[i] = pP[i] ? *(const float4*)(pP[i] + (kt) + cA)             \
                            : make_float4(0.f, 0.f, 0.f, 0.f);                \
        }                                                                     \
        _Pragma("unroll")                                                     \
        for (int i = 0; i < 2; i++)                                           \
            wReg[i] = *(const float4*)(pW[i] + (kt) + cA);                    \
    } while (0)

#define STORE(buf)                                                            \
    do {                                                                      \
        _Pragma("unroll")                                                     \
        for (int i = 0; i < 4; i++) {                                         \
            unsigned* p = smA + (buf) * 4096 + baseA[i];                      \
            p[0]  = f2tf(aReg[i].x + pReg[i].x);                              \
            p[4]  = f2tf(aReg[i].y + pReg[i].y);                              \
            p[8]  = f2tf(aReg[i].z + pReg[i].z);                              \
            p[12] = f2tf(aReg[i].w + pReg[i].w);                              \
        }                                                                     \
        _Pragma("unroll")                                                     \
        for (int i = 0; i < 2; i++) {                                         \
            unsigned* p = smW + (buf) * 2048 + baseW[i];                      \
            p[0] = f2tf(wReg[i].x);                                           \
            p[2] = f2tf(wReg[i].y);                                           \
            p[4] = f2tf(wReg[i].z);                                           \
            p[6] = f2tf(wReg[i].w);                                           \
        }                                                                     \
    } while (0)

    float acc[2][4][4] = {};

    PREFETCH(0);
    STORE(0);
    __syncthreads();

    const uint4* As4 = (const uint4*)smA;   // [2][1024]
    const uint2* Ws2 = (const uint2*)smW;   // [2][1024]

    const int NT = CDIM / 32;              // 12
    for (int kt = 0; kt < NT; kt++) {
        const int cur = kt & 1;
        if (kt + 1 < NT) PREFETCH((kt + 1) * 32);

#pragma unroll
        for (int ks = 0; ks < 4; ks++) {
            uint4 av[2];
            uint2 bv[4];
#pragma unroll
            for (int mt = 0; mt < 2; mt++)
                av[mt] = As4[cur * 1024 + ((wm * 2 + mt) * 4 + ks) * 32 + lane];
#pragma unroll
            for (int nt = 0; nt < 4; nt++)
                bv[nt] = Ws2[cur * 1024 + ((wn * 4 + nt) * 4 + ks) * 32 + lane];
#pragma unroll
            for (int mt = 0; mt < 2; mt++)
#pragma unroll
                for (int nt = 0; nt < 4; nt++)
                    mma8(acc[mt][nt], (const unsigned*)&av[mt], (const unsigned*)&bv[nt]);
        }

        if (kt + 1 < NT) STORE(cur ^ 1);
        __syncthreads();
    }

    // ---- epilogue ----
#pragma unroll
    for (int mt = 0; mt < 2; mt++) {
#pragma unroll
        for (int nt = 0; nt < 4; nt++) {
            const int col = j0 + wn * 32 + nt * 8 + tl * 2;
            const int r0 = m0 + wm * 32 + mt * 16 + g;
            const int r1 = r0 + 8;
            float* a = acc[mt][nt];
            if (mode == 3) {
                const float b0 = bias ? bias[col]     : 0.f;
                const float b1 = bias ? bias[col + 1] : 0.f;
                if (r0 < rows)
                    *(float2*)&out_param[r0 * CDIM + col] = make_float2(a[0] + b0, a[1] + b1);
                if (r1 < rows)
                    *(float2*)&out_param[r1 * CDIM + col] = make_float2(a[2] + b0, a[3] + b1);
            } else if (mode == 0) {
                if (r0 < rows) {
                    g_qf[qf_idx(r0, col)]     = f2tf(a[0] * 0.125f);
                    g_qf[qf_idx(r0, col + 1)] = f2tf(a[1] * 0.125f);
                }
                if (r1 < rows) {
                    g_qf[qf_idx(r1, col)]     = f2tf(a[2] * 0.125f);
                    g_qf[qf_idx(r1, col + 1)] = f2tf(a[3] * 0.125f);
                }
            } else if (mode == 1) {
                if (r0 < rows) {
                    g_kf[kf_idx(r0, col)]     = f2tf(a[0]);
                    g_kf[kf_idx(r0, col + 1)] = f2tf(a[1]);
                }
                if (r1 < rows) {
                    g_kf[kf_idx(r1, col)]     = f2tf(a[2]);
                    g_kf[kf_idx(r1, col + 1)] = f2tf(a[3]);
                }
            } else {
                if (r0 < rows) {
                    g_vf[vf_idx(r0, col)]     = f2tf(a[0]);
                    g_vf[vf_idx(r0, col + 1)] = f2tf(a[1]);
                }
                if (r1 < rows) {
                    g_vf[vf_idx(r1, col)]     = f2tf(a[2]);
                    g_vf[vf_idx(r1, col + 1)] = f2tf(a[3]);
                }
            }
        }
    }
}

// ---------------- 4) tf32 flash attention (fragment-major, cp.async) -------
// grid (ceil(N/128), HEADS), block 256 (8 warps x 16 q-rows each)
// smem (words): Qfrag[8192] | Kfrag[2][4096] | Vfrag[2][4096] | P[128][68]
#define K_OFF 8192
#define V_OFF 16384
#define P_OFF 24576
#define ATTN_SMEM ((P_OFF + 128 * 68) * (int)sizeof(unsigned))

__global__ __launch_bounds__(256)
void attn_tc()
{
    extern __shared__ unsigned sm[];
    unsigned* Ps = sm + P_OFF;

    const int h  = blockIdx.y;
    const int M  = g_M;
    const int tid = threadIdx.x, warp = tid >> 5, lane = tid & 31;
    const int g = lane >> 2, t = lane & 3;
    const int rb = warp * 16;
    const unsigned smB = (unsigned)__cvta_generic_to_shared(sm);

    // ---- stage Q fragments (contiguous 32KB) ----
    const unsigned* srcQ = g_qf + h * HSTR_Q + blockIdx.x * 8192;
#pragma unroll
    for (int i = 0; i < 8; i++) {
        const int c = tid + i * 256;
        cp16(smB + c * 16u, srcQ + c * 4);
    }

#define STAGE_KV(kt, buf)                                                     \
    do {                                                                      \
        const unsigned* srcK = g_kf + h * HSTR_K + (kt) * 4096;               \
        const unsigned* srcV = g_vf + h * HSTR_K + (kt) * 4096;               \
        _Pragma("unroll")                                                     \
        for (int i = 0; i < 4; i++) {                                         \
            const int c = tid + i * 256;                                      \
            cp16(smB + (K_OFF + (buf) * 4096) * 4u + c * 16u, srcK + c * 4);  \
            cp16(smB + (V_OFF + (buf) * 4096) * 4u + c * 16u, srcV + c * 4);  \
        }                                                                     \
    } while (0)

    const int nT = (M + 63) >> 6;
    STAGE_KV(0, 0);
    CP_COMMIT();                           // group: Q + tile0

    float m_lo = -1e30f, m_hi = -1e30f, l_lo = 0.f, l_hi = 0.f;
    float co[8][4] = {};

    const uint4* Qf4 = (const uint4*)sm;   // 2048 entries

    for (int kt = 0; kt < nT; kt++) {
        const int cur = kt & 1;
        __syncthreads();                   // all warps done with buffer cur^1
        if (kt + 1 < nT) {
            STAGE_KV(kt + 1, cur ^ 1);
            CP_COMMIT();
            CP_WAIT(1);
        } else {
            CP_WAIT(0);
        }
        __syncthreads();

        const uint2* Kf2 = (const uint2*)(sm + K_OFF + cur * 4096);
        const uint2* Vf2 = (const uint2*)(sm + V_OFF + cur * 4096);

        // ---- S = Q K^T : warp's 16 rows x 64 cols ----
        float cs[8][4] = {};
#pragma unroll
        for (int ks = 0; ks < 8; ks++) {
            const uint4 a4 = Qf4[(warp * 8 + ks) * 32 + lane];
#pragma unroll
            for (int nt = 0; nt < 8; nt++) {
                const uint2 b2 = Kf2[(nt * 8 + ks) * 32 + lane];
                mma8(cs[nt], (const unsigned*)&a4, (const unsigned*)&b2);
            }
        }

        // ---- online softmax ----
        float tm_lo = -1e30f, tm_hi = -1e30f;
#pragma unroll
        for (int nt = 0; nt < 8; nt++) {
            const int c0 = kt * 64 + nt * 8 + t * 2;
            if (c0     >= M) { cs[nt][0] = -1e30f; cs[nt][2] = -1e30f; }
            if (c0 + 1 >= M) { cs[nt][1] = -1e30f; cs[nt][3] = -1e30f; }
            tm_lo = fmaxf(tm_lo, fmaxf(cs[nt][0], cs[nt][1]));
            tm_hi = fmaxf(tm_hi, fmaxf(cs[nt][2], cs[nt][3]));
        }
        tm_lo = fmaxf(tm_lo, __shfl_xor_sync(0xffffffffu, tm_lo, 1));
        tm_lo = fmaxf(tm_lo, __shfl_xor_sync(0xffffffffu, tm_lo, 2));
        tm_hi = fmaxf(tm_hi, __shfl_xor_sync(0xffffffffu, tm_hi, 1));
        tm_hi = fmaxf(tm_hi, __shfl_xor_sync(0xffffffffu, tm_hi, 2));

        const float mn_lo = fmaxf(m_lo, tm_lo);
        const float mn_hi = fmaxf(m_hi, tm_hi);
        const float corr_lo = __expf(m_lo - mn_lo);
        const float corr_hi = __expf(m_hi - mn_hi);
        m_lo = mn_lo; m_hi = mn_hi;

        float rs_lo = 0.f, rs_hi = 0.f;
#pragma unroll
        for (int nt = 0; nt < 8; nt++) {
            const float p0 = __expf(cs[nt][0] - mn_lo);
            const float p1 = __expf(cs[nt][1] - mn_lo);
            const float p2 = __expf(cs[nt][2] - mn_hi);
            const float p3 = __expf(cs[nt][3] - mn_hi);
            rs_lo += p0 + p1;
            rs_hi += p2 + p3;
            const int col = nt * 8 + t * 2;
            *(uint2*)&Ps[(rb + g    ) * 68 + col] = make_uint2(f2tf(p0), f2tf(p1));
            *(uint2*)&Ps[(rb + g + 8) * 68 + col] = make_uint2(f2tf(p2), f2tf(p3));
        }
        rs_lo += __shfl_xor_sync(0xffffffffu, rs_lo, 1);
        rs_lo += __shfl_xor_sync(0xffffffffu, rs_lo, 2);
        rs_hi += __shfl_xor_sync(0xffffffffu, rs_hi, 1);
        rs_hi += __shfl_xor_sync(0xffffffffu, rs_hi, 2);
        l_lo = l_lo * corr_lo + rs_lo;
        l_hi = l_hi * corr_hi + rs_hi;

#pragma unroll
        for (int nt = 0; nt < 8; nt++) {
            co[nt][0] *= corr_lo; co[nt][1] *= corr_lo;
            co[nt][2] *= corr_hi; co[nt][3] *= corr_hi;
        }
        __syncwarp();    // order Ps stores (cross-lane) before A-frag loads

        // ---- O += P V ----
#pragma unroll
        for (int ks = 0; ks < 8; ks++) {
            unsigned a[4];
            a[0] = Ps[(rb + g    ) * 68 + ks * 8 + t    ];
            a[1] = Ps[(rb + g + 8) * 68 + ks * 8 + t    ];
            a[2] = Ps[(rb + g    ) * 68 + ks * 8 + t + 4];
            a[3] = Ps[(rb + g + 8) * 68 + ks * 8 + t + 4];
#pragma unroll
            for (int nt = 0; nt < 8; nt++) {
                const uint2 b2 = Vf2[(nt * 8 + ks) * 32 + lane];
                mma8(co[nt], a, (const unsigned*)&b2);
            }
        }
    }

    // ---- normalize + store (row-major g_o for out-proj) ----
    const float inv_lo = 1.0f / l_lo;
    const float inv_hi = 1.0f / l_hi;
    const int q0 = blockIdx.x * 128;
#pragma unroll
    for (int nt = 0; nt < 8; nt++) {
        const int d  = nt * 8 + t * 2;
        const int r0 = q0 + rb + g;
        const int r1 = r0 + 8;
        if (r0 < N_Q)
            *(float2*)&g_o[r0 * CDIM + h * HDIM + d] =
                make_float2(co[nt][0] * inv_lo, co[nt][1] * inv_lo);
        if (r1 < N_Q)
            *(float2*)&g_o[r1 * CDIM + h * HDIM + d] =
                make_float2(co[nt][2] * inv_hi, co[nt][3] * inv_hi);
    }
#undef STAGE_KV
}

// ---------------- launch ---------------------------------------------------
extern "C" void kernel_launch(void* const* d_in, const int* in_sizes, int n_in,
                              void* d_out, int out_size)
{
    const float* x          = (const float*)d_in[0];
    const float* pos        = (const float*)d_in[1];
    const float* mask       = (const float*)d_in[2];
    const float* mask_block = (const float*)d_in[3];
    const float* Wq         = (const float*)d_in[4];
    const float* Wk         = (const float*)d_in[5];
    const float* Wv         = (const float*)d_in[6];
    const float* Wp         = (const float*)d_in[7];
    const float* bp         = (const float*)d_in[8];
    float* out = (float*)d_out;

    cudaFuncSetAttribute(attn_tc, cudaFuncAttributeMaxDynamicSharedMemorySize, ATTN_SMEM);
    cudaFuncSetAttribute(proj_tc, cudaFuncAttributeMaxDynamicSharedMemorySize, PROJ_SMEM);

    pool_kernel<<<64, CDIM>>>(x, mask);
    back_finalize_kernel<<<1, CDIM>>>();
    scan_kernel<<<1, 1024>>>(mask, mask_block);

    // fused Q/K/V projection: blockIdx.z = mode 0/1/2
    dim3 gqkv((N_Q + 127) / 128, CDIM / 64, 3);   // 33 x 6 x 3
    proj_tc<<<gqkv, 256, PROJ_SMEM>>>(0, x, pos, Wq, Wk, Wv, Wp, nullptr, nullptr);

    dim3 gattn((N_Q + 127) / 128, HEADS);         // 33 x 6
    attn_tc<<<gattn, 256, ATTN_SMEM>>>();

    // output projection
    dim3 gout((N_Q + 127) / 128, CDIM / 64, 1);
    proj_tc<<<gout, 256, PROJ_SMEM>>>(3, x, pos, Wq, Wk, Wv, Wp, bp, out);
}